// round 16
// baseline (speedup 1.0000x reference)
#include <cuda_runtime.h>
#include <cuda_bf16.h>
#include <cstdint>

// ---------------- problem constants ----------------
constexpr int N_USERS  = 29858;
constexpr int N_ITEMS  = 40981;
constexpr int N_TOT    = 70839;
constexpr int D        = 64;
constexpr int F        = 512;
constexpr int NPAD     = 70912;                 // 554 * 128
constexpr int NU_ELEMS = N_USERS * D;
constexpr int NTOT4    = N_TOT * D / 4;

constexpr int KC           = 32;                // K per pipeline chunk
constexpr int CH_TOT       = NPAD / KC;         // 2216
constexpr int KSPLITS      = 74;                // GEMM1 split-K (grid 296)
constexpr int CH_PER_SPLIT = (CH_TOT + KSPLITS - 1) / KSPLITS;  // 30

constexpr int EW_BLOCKS   = (NTOT4 + 255) / 256;          // 4427
constexpr int PREP_BLOCKS = (int)((size_t)NPAD * F / 8 / 256);  // 17728

// smem stage: Ah 8K | Al 8K | Bh 4K | Bl 4K = 24 KB; 4 slots = 96 KB
constexpr int A_OFF_L = 8192;
constexpr int B_OFF_H = 16384;
constexpr int B_OFF_L = 20480;
constexpr int STAGE   = 24576;
constexpr int NSTAGE  = 4;
constexpr int GEMM_SMEM = NSTAGE * STAGE + 1024;

// ---------------- scratch (static device globals; no allocation) -------------
__device__ __align__(128) unsigned short g_e0h[(size_t)NPAD * D];  // E0 hi [n][64]
__device__ __align__(128) unsigned short g_e0l[(size_t)NPAD * D];  // E0 lo
__device__ __align__(128) unsigned short g_eh[(size_t)NPAD * D];   // E_l hi (BSS pad=0)
__device__ __align__(128) unsigned short g_el[(size_t)NPAD * D];   // E_l lo
__device__ __align__(128) unsigned short g_vh[(size_t)NPAD * F];   // V hi [n][512]
__device__ __align__(128) unsigned short g_vl[(size_t)NPAD * F];   // V lo
__device__ __align__(128) unsigned short g_wh[F * D];              // W hi [512 f][64 d]
__device__ __align__(128) unsigned short g_wl[F * D];              // W lo
__device__ __align__(128) float          g_ws[F * D];              // Wsum [f][d]
__device__ __align__(128) float          g_p1[KSPLITS * 4 * 128 * D];

// ---------------- helpers ----------------
__device__ __forceinline__ uint32_t smem_u32(const void* p) {
    uint32_t a;
    asm("{ .reg .u64 t; cvta.to.shared.u64 t, %1; cvt.u32.u64 %0, t; }"
        : "=r"(a) : "l"(p));
    return a;
}
__device__ __forceinline__ uint32_t swz(uint32_t o) { return o ^ ((o >> 3) & 0x70); }

__device__ __forceinline__ void cp16(uint32_t dst, const void* src) {
    asm volatile("cp.async.cg.shared.global [%0], [%1], 16;"
                 :: "r"(dst), "l"(src) : "memory");
}
__device__ __forceinline__ void cp_commit() {
    asm volatile("cp.async.commit_group;" ::: "memory");
}
template <int N>
__device__ __forceinline__ void cp_wait() {
    asm volatile("cp.async.wait_group %0;" :: "n"(N) : "memory");
}

__device__ __forceinline__ void split4(const float4& x, uint2& hi, uint2& lo) {
    float v[4] = {x.x, x.y, x.z, x.w};
    unsigned int hw[2], lw[2];
#pragma unroll
    for (int p = 0; p < 2; p++) {
        __nv_bfloat16 h0 = __float2bfloat16(v[2 * p]);
        __nv_bfloat16 h1 = __float2bfloat16(v[2 * p + 1]);
        float r0 = v[2 * p]     - __bfloat162float(h0);
        float r1 = v[2 * p + 1] - __bfloat162float(h1);
        hw[p] = (unsigned)__bfloat16_as_ushort(h0) |
                ((unsigned)__bfloat16_as_ushort(h1) << 16);
        lw[p] = (unsigned)__bfloat16_as_ushort(__float2bfloat16(r0)) |
                ((unsigned)__bfloat16_as_ushort(__float2bfloat16(r1)) << 16);
    }
    hi = make_uint2(hw[0], hw[1]);
    lo = make_uint2(lw[0], lw[1]);
}

__device__ __forceinline__ void ldsm_x4(uint32_t* r, uint32_t a) {
    asm volatile("ldmatrix.sync.aligned.m8n8.x4.shared.b16 {%0,%1,%2,%3}, [%4];"
                 : "=r"(r[0]), "=r"(r[1]), "=r"(r[2]), "=r"(r[3]) : "r"(a));
}
__device__ __forceinline__ void ldsm_x4_t(uint32_t* r, uint32_t a) {
    asm volatile("ldmatrix.sync.aligned.m8n8.x4.trans.shared.b16 {%0,%1,%2,%3}, [%4];"
                 : "=r"(r[0]), "=r"(r[1]), "=r"(r[2]), "=r"(r[3]) : "r"(a));
}
__device__ __forceinline__ void mma_bf16(float* c, const uint32_t* a,
                                         uint32_t b0, uint32_t b1) {
    asm volatile(
        "mma.sync.aligned.m16n8k16.row.col.f32.bf16.bf16.f32 "
        "{%0,%1,%2,%3}, {%4,%5,%6,%7}, {%8,%9}, {%0,%1,%2,%3};"
        : "+f"(c[0]), "+f"(c[1]), "+f"(c[2]), "+f"(c[3])
        : "r"(a[0]), "r"(a[1]), "r"(a[2]), "r"(a[3]), "r"(b0), "r"(b1));
}

// reconstruct fp32 pair from packed bf16 hi/lo words
__device__ __forceinline__ float2 bfpair(unsigned int h, unsigned int l) {
    float hx = __bfloat162float(__ushort_as_bfloat16((unsigned short)(h & 0xffff)));
    float hy = __bfloat162float(__ushort_as_bfloat16((unsigned short)(h >> 16)));
    float lx = __bfloat162float(__ushort_as_bfloat16((unsigned short)(l & 0xffff)));
    float ly = __bfloat162float(__ushort_as_bfloat16((unsigned short)(l >> 16)));
    return make_float2(hx + lx, hy + ly);
}

// ---------------- K0: E0 hi/lo split + V hi/lo split (merged launch) ---------
__global__ void k_init_prep(const float* __restrict__ u, const float* __restrict__ it,
                            const float* __restrict__ v) {
    if (blockIdx.x < EW_BLOCKS) {
        int i = blockIdx.x * blockDim.x + threadIdx.x;
        if (i < (NPAD - N_TOT) * D / 4) {
            uint2 z = make_uint2(0u, 0u);
            *(uint2*)(g_e0h + (size_t)N_TOT * D + i * 4) = z;
            *(uint2*)(g_e0l + (size_t)N_TOT * D + i * 4) = z;
        }
        if (i >= NTOT4) return;
        int e = i << 2;
        float4 t;
        if (e < NU_ELEMS) t = *(const float4*)(u + e);
        else              t = *(const float4*)(it + (e - NU_ELEMS));
        uint2 hi, lo;
        split4(t, hi, lo);
        *(uint2*)(g_e0h + e) = hi;
        *(uint2*)(g_e0l + e) = lo;
    } else {
        size_t i = (size_t)(blockIdx.x - EW_BLOCKS) * blockDim.x + threadIdx.x;
        size_t e = i * 8;
        int n = (int)(e >> 9);
        uint2 h0, l0, h1, l1;
        if (n < N_TOT) {
            float4 x0 = *(const float4*)(v + e);
            float4 x1 = *(const float4*)(v + e + 4);
            split4(x0, h0, l0);
            split4(x1, h1, l1);
        } else {
            h0 = l0 = h1 = l1 = make_uint2(0u, 0u);
        }
        *(uint4*)(g_vh + e) = make_uint4(h0.x, h0.y, h1.x, h1.y);
        *(uint4*)(g_vl + e) = make_uint4(l0.x, l0.y, l1.x, l1.y);
    }
}

// ---------------- reduce partials -> W_l ; wh/wl [f][d] ; Wsum ---------------
template <int L>
__global__ void k_reduce1(const float* __restrict__ filt) {
    __shared__ float2 buf[8][32];
    const int f   = blockIdx.x;                 // 0..511
    const int sub = threadIdx.x >> 5;           // warp id = 0..7
    const int d2  = threadIdx.x & 31;           // float2 column
    const int mt  = f >> 7, fl = f & 127;
    const float* base = g_p1 + fl * 64 + d2 * 2;

    float2 s = make_float2(0.f, 0.f);
    for (int ks = sub; ks < KSPLITS; ks += 8) {
        float2 t = *(const float2*)(base + (size_t)((ks << 2) + mt) * 8192);
        s.x += t.x; s.y += t.y;
    }
    buf[sub][d2] = s;
    __syncthreads();
    if (sub != 0) return;

#pragma unroll
    for (int k = 1; k < 8; k++) {
        float2 t = buf[k][d2];
        s.x += t.x; s.y += t.y;
    }
    float fc = filt[f];
    s.x *= fc; s.y *= fc;
    float* wsp = g_ws + f * 64 + d2 * 2;
    float2 tot = s;
    if (L == 0) {
        *(float2*)wsp = s;
    } else {
        float2 o = *(const float2*)wsp;
        tot = make_float2(o.x + s.x, o.y + s.y);
        if (L == 1) *(float2*)wsp = tot;
    }
    float2 wv = (L < 2) ? s : tot;
    __nv_bfloat16 hx = __float2bfloat16(wv.x);
    __nv_bfloat16 hy = __float2bfloat16(wv.y);
    float rx = wv.x - __bfloat162float(hx);
    float ry = wv.y - __bfloat162float(hy);
    unsigned int hw = (unsigned)__bfloat16_as_ushort(hx) |
                      ((unsigned)__bfloat16_as_ushort(hy) << 16);
    unsigned int lw = (unsigned)__bfloat16_as_ushort(__float2bfloat16(rx)) |
                      ((unsigned)__bfloat16_as_ushort(__float2bfloat16(ry)) << 16);
    *(unsigned int*)(g_wh + f * 64 + d2 * 2) = hw;
    *(unsigned int*)(g_wl + f * 64 + d2 * 2) = lw;
}

// ---------------- pipelined warp-MMA GEMM ----------------
// C[128 x 64] = A[128 x K] * B[64 x K]^T, hi/lo bf16 split (3 MMA terms)
// MODE 0: GEMM1, B = E0 pair   -> g_p1 partial      (A trans from [n][512])
// MODE 3: GEMM1, B = E_l pair  -> g_p1 partial
// MODE 1: GEMM2, B = W [f][d]  -> writes E hi/lo    (A plain; B trans path)
// MODE 2: final, B = Wsum[f][d]-> out = (E0 + C)/4
template <int MODE>
__global__ __launch_bounds__(256, 2) void k_gemm(float* __restrict__ outp) {
    constexpr bool G1 = (MODE == 0 || MODE == 3);
    extern __shared__ char smraw[];
    const uint32_t sm0 = (smem_u32(smraw) + 1023) & ~1023u;

    const int tid  = threadIdx.x;
    const int w    = tid >> 5;
    const int lane = tid & 31;

    int m0, c0, nc;
    if (G1) {
        int mt = blockIdx.x & 3;
        int ks = blockIdx.x >> 2;
        m0 = mt * 128;                         // f-tile origin
        c0 = ks * CH_PER_SPLIT;
        nc = min(CH_PER_SPLIT, CH_TOT - c0);
    } else {
        m0 = blockIdx.x * 128;                 // n-tile origin
        c0 = 0;
        nc = F / KC;                           // 16
    }

    const unsigned short* bhp = (MODE == 0) ? g_e0h : (MODE == 3) ? g_eh : g_wh;
    const unsigned short* blp = (MODE == 0) ? g_e0l : (MODE == 3) ? g_el : g_wl;

    float acc[8][4];
#pragma unroll
    for (int nt = 0; nt < 8; nt++)
#pragma unroll
        for (int j = 0; j < 4; j++) acc[nt][j] = 0.f;

    auto stage = [&](int ch) {
        if (ch >= nc) return;
        const int k0 = (c0 + ch) * KC;
        const uint32_t sbuf = sm0 + (uint32_t)(ch & 3) * STAGE;
        if (G1) {
            for (int j = tid; j < 512; j += 256) {
                int n = j >> 4, seg = (j >> 3) & 1, q = j & 7;
                size_t src = (size_t)(k0 + n) * F + m0 + seg * 64 + q * 8;
                uint32_t d = seg * 4096 + swz(n * 128 + q * 16);
                cp16(sbuf + d,           g_vh + src);
                cp16(sbuf + A_OFF_L + d, g_vl + src);
            }
            {
                int n = tid >> 3, q = tid & 7;
                size_t src = (size_t)(k0 + n) * D + q * 8;
                uint32_t d = swz(n * 128 + q * 16);
                cp16(sbuf + B_OFF_H + d, bhp + src);
                cp16(sbuf + B_OFF_L + d, blp + src);
            }
        } else {
            for (int j = tid; j < 512; j += 256) {
                int m = j >> 2, q = j & 3;
                size_t src = (size_t)(m0 + m) * F + k0 + q * 8;
                uint32_t d = swz(m * 64 + q * 16);
                cp16(sbuf + d,           g_vh + src);
                cp16(sbuf + A_OFF_L + d, g_vl + src);
            }
            {
                // B = W rows [KC f][64 d], 128B rows (same shape as G1's B)
                int row = tid >> 3, q = tid & 7;
                size_t src = (size_t)(k0 + row) * D + q * 8;
                uint32_t d = swz(row * 128 + q * 16);
                cp16(sbuf + B_OFF_H + d, bhp + src);
                cp16(sbuf + B_OFF_L + d, blp + src);
            }
        }
    };

    // fragment addressing
    const int a_k   = (lane & 7) | ((lane & 16) >> 1);        // G1 (trans A)
    const uint32_t a_seg = (uint32_t)(w >> 2) * 4096;
    const uint32_t a_f2  = (uint32_t)((w * 16 + (lane & 8)) & 63) * 2;
    const int bt_k  = lane & 15;                              // trans B (all modes)
    const int bt_n8 = ((lane >> 4) & 1) * 8;
    const int a_row  = w * 16 + (lane & 15);                  // plain A
    const int a_colh = (lane >> 4) * 8;

    auto compute = [&](int ch) {
        const uint32_t buf = sm0 + (uint32_t)(ch & 3) * STAGE;
        const uint32_t sAh = buf, sAl = buf + A_OFF_L;
        const uint32_t sBh = buf + B_OFF_H, sBl = buf + B_OFF_L;
#pragma unroll
        for (int ks = 0; ks < KC / 16; ks++) {
            uint32_t ah[4], al[4];
            if (G1) {
                uint32_t ao = a_seg + swz((uint32_t)((ks * 16 + a_k) * 128) + a_f2);
                ldsm_x4_t(ah, sAh + ao);
                ldsm_x4_t(al, sAl + ao);
            } else {
                uint32_t ao = swz((uint32_t)(a_row * 64 + (ks * 16 + a_colh) * 2));
                ldsm_x4(ah, sAh + ao);
                ldsm_x4(al, sAl + ao);
            }
#pragma unroll
            for (int nt2 = 0; nt2 < 4; nt2++) {
                uint32_t bh[4], bl[4];
                uint32_t bo = swz((uint32_t)((ks * 16 + bt_k) * 128 +
                                             (nt2 * 16 + bt_n8) * 2));
                ldsm_x4_t(bh, sBh + bo);
                ldsm_x4_t(bl, sBl + bo);
                float* cE = acc[2 * nt2];
                float* cO = acc[2 * nt2 + 1];
                mma_bf16(cE, ah, bh[0], bh[1]);
                mma_bf16(cE, ah, bl[0], bl[1]);
                mma_bf16(cE, al, bh[0], bh[1]);
                mma_bf16(cO, ah, bh[2], bh[3]);
                mma_bf16(cO, ah, bl[2], bl[3]);
                mma_bf16(cO, al, bh[2], bh[3]);
            }
        }
    };

    // ---- pipeline: 4 slots, lookahead 2, SINGLE barrier per chunk ----
    // Safety: slot s read at iter s (compute), next written at iter s+2's
    // stage (before that iter's sync) -> the iter s+1 sync separates them.
    // Visibility: group of stage(ch) completes at iter ch's wait<2>; the
    // following sync publishes it. No barrier between compute(ch) and
    // stage(ch+3): fast warps stream next loads under slow warps' MMAs.
    stage(0);
    cp_commit();
    stage(1);
    cp_commit();
    for (int ch = 0; ch < nc; ch++) {
        stage(ch + 2);
        cp_commit();
        cp_wait<2>();
        __syncthreads();
        compute(ch);
    }

    // ---- epilogue ----
    const int r0   = w * 16 + (lane >> 2);
    const int ncol = 2 * (lane & 3);
    if (G1) {
        float* out = g_p1 + (size_t)blockIdx.x * 8192;
#pragma unroll
        for (int nt = 0; nt < 8; nt++) {
            int n = nt * 8 + ncol;
            *(float2*)(out + r0 * 64 + n)       = make_float2(acc[nt][0], acc[nt][1]);
            *(float2*)(out + (r0 + 8) * 64 + n) = make_float2(acc[nt][2], acc[nt][3]);
        }
    } else if (MODE == 1) {
#pragma unroll
        for (int half = 0; half < 2; half++) {
            int m = m0 + r0 + half * 8;
            if (m >= N_TOT) continue;
            unsigned short* ehp = g_eh + (size_t)m * D;
            unsigned short* elp = g_el + (size_t)m * D;
#pragma unroll
            for (int nt = 0; nt < 8; nt++) {
                int n = nt * 8 + ncol;
                float cx = acc[nt][half * 2], cy = acc[nt][half * 2 + 1];
                __nv_bfloat16 hx = __float2bfloat16(cx);
                __nv_bfloat16 hy = __float2bfloat16(cy);
                float rx = cx - __bfloat162float(hx);
                float ry = cy - __bfloat162float(hy);
                unsigned int hw = (unsigned)__bfloat16_as_ushort(hx) |
                                  ((unsigned)__bfloat16_as_ushort(hy) << 16);
                unsigned int lw = (unsigned)__bfloat16_as_ushort(__float2bfloat16(rx)) |
                                  ((unsigned)__bfloat16_as_ushort(__float2bfloat16(ry)) << 16);
                *(unsigned int*)(ehp + n) = hw;
                *(unsigned int*)(elp + n) = lw;
            }
        }
    } else {   // MODE 2: out = (E0 + C)/4
#pragma unroll
        for (int half = 0; half < 2; half++) {
            int m = m0 + r0 + half * 8;
            if (m >= N_TOT) continue;
            const unsigned short* e0hp = g_e0h + (size_t)m * D;
            const unsigned short* e0lp = g_e0l + (size_t)m * D;
            float* op = outp + (size_t)m * D;
#pragma unroll
            for (int nt = 0; nt < 8; nt++) {
                int n = nt * 8 + ncol;
                float cx = acc[nt][half * 2], cy = acc[nt][half * 2 + 1];
                unsigned int hv = *(const unsigned int*)(e0hp + n);
                unsigned int lv = *(const unsigned int*)(e0lp + n);
                float2 e = bfpair(hv, lv);
                *(float2*)(op + n) = make_float2((e.x + cx) * 0.25f,
                                                 (e.y + cy) * 0.25f);
            }
        }
    }
}

// ---------------- launcher ----------------
extern "C" void kernel_launch(void* const* d_in, const int* in_sizes, int n_in,
                              void* d_out, int out_size) {
    const float* user    = (const float*)d_in[0];
    const float* item    = (const float*)d_in[1];
    const float* v       = (const float*)d_in[2];
    const float* filters = (const float*)d_in[3];
    float* out = (float*)d_out;

    cudaFuncSetAttribute(k_gemm<0>, cudaFuncAttributeMaxDynamicSharedMemorySize, GEMM_SMEM);
    cudaFuncSetAttribute(k_gemm<1>, cudaFuncAttributeMaxDynamicSharedMemorySize, GEMM_SMEM);
    cudaFuncSetAttribute(k_gemm<2>, cudaFuncAttributeMaxDynamicSharedMemorySize, GEMM_SMEM);
    cudaFuncSetAttribute(k_gemm<3>, cudaFuncAttributeMaxDynamicSharedMemorySize, GEMM_SMEM);

    k_init_prep<<<EW_BLOCKS + PREP_BLOCKS, 256>>>(user, item, v);

    // layer 1
    k_gemm<0><<<KSPLITS * 4, 256, GEMM_SMEM>>>(nullptr);   // P1 = V^T E0
    k_reduce1<0><<<512, 256>>>(filters);                   // W1; ws = W1
    k_gemm<1><<<NPAD / 128, 256, GEMM_SMEM>>>(nullptr);    // E1 = V W1
    // layer 2
    k_gemm<3><<<KSPLITS * 4, 256, GEMM_SMEM>>>(nullptr);   // P2 = V^T E1
    k_reduce1<1><<<512, 256>>>(filters + F);               // W2; ws += W2
    k_gemm<1><<<NPAD / 128, 256, GEMM_SMEM>>>(nullptr);    // E2 = V W2
    // layer 3
    k_gemm<3><<<KSPLITS * 4, 256, GEMM_SMEM>>>(nullptr);   // P3 = V^T E2
    k_reduce1<2><<<512, 256>>>(filters + 2 * F);           // Wsum hi/lo (merged)

    k_gemm<2><<<NPAD / 128, 256, GEMM_SMEM>>>(out);        // out = (E0 + V Wsum)/4
}

// round 17
// speedup vs baseline: 1.0186x; 1.0186x over previous
#include <cuda_runtime.h>
#include <cuda_bf16.h>
#include <cstdint>

// ---------------- problem constants ----------------
constexpr int N_USERS  = 29858;
constexpr int N_ITEMS  = 40981;
constexpr int N_TOT    = 70839;
constexpr int D        = 64;
constexpr int F        = 512;
constexpr int NPAD     = 70912;                 // 554 * 128
constexpr int NU_ELEMS = N_USERS * D;
constexpr int NTOT4    = N_TOT * D / 4;

constexpr int KC           = 32;                // K per pipeline chunk
constexpr int CH_TOT       = NPAD / KC;         // 2216
constexpr int KSPLITS      = 111;               // GEMM1 split-K (grid 444 = 3/SM)
constexpr int CH_PER_SPLIT = (CH_TOT + KSPLITS - 1) / KSPLITS;  // 20

constexpr int EW_BLOCKS   = (NTOT4 + 255) / 256;          // 4427
constexpr int PREP_BLOCKS = (int)((size_t)NPAD * F / 8 / 256);  // 17728

// smem stage: Ah 8K | Al 8K | Bh 4K | Bl 4K = 24 KB; 3 slots = 72 KB
constexpr int A_OFF_L = 8192;
constexpr int B_OFF_H = 16384;
constexpr int B_OFF_L = 20480;
constexpr int STAGE   = 24576;
constexpr int NSTAGE  = 3;
constexpr int GEMM_SMEM = NSTAGE * STAGE + 1024;   // 74752 (3 CTAs fit 228 KB)

// ---------------- scratch (static device globals; no allocation) -------------
__device__ __align__(128) unsigned short g_e0h[(size_t)NPAD * D];  // E0 hi [n][64]
__device__ __align__(128) unsigned short g_e0l[(size_t)NPAD * D];  // E0 lo
__device__ __align__(128) unsigned short g_eh[(size_t)NPAD * D];   // E_l hi (BSS pad=0)
__device__ __align__(128) unsigned short g_el[(size_t)NPAD * D];   // E_l lo
__device__ __align__(128) unsigned short g_vh[(size_t)NPAD * F];   // V hi [n][512]
__device__ __align__(128) unsigned short g_vl[(size_t)NPAD * F];   // V lo
__device__ __align__(128) unsigned short g_wh[F * D];              // W hi [512 f][64 d]
__device__ __align__(128) unsigned short g_wl[F * D];              // W lo
__device__ __align__(128) float          g_ws[F * D];              // Wsum [f][d]
__device__ __align__(128) float          g_p1[KSPLITS * 4 * 128 * D];

// ---------------- helpers ----------------
__device__ __forceinline__ uint32_t smem_u32(const void* p) {
    uint32_t a;
    asm("{ .reg .u64 t; cvta.to.shared.u64 t, %1; cvt.u32.u64 %0, t; }"
        : "=r"(a) : "l"(p));
    return a;
}
__device__ __forceinline__ uint32_t swz(uint32_t o) { return o ^ ((o >> 3) & 0x70); }

__device__ __forceinline__ void cp16(uint32_t dst, const void* src) {
    asm volatile("cp.async.cg.shared.global [%0], [%1], 16;"
                 :: "r"(dst), "l"(src) : "memory");
}
__device__ __forceinline__ void cp_commit() {
    asm volatile("cp.async.commit_group;" ::: "memory");
}
template <int N>
__device__ __forceinline__ void cp_wait() {
    asm volatile("cp.async.wait_group %0;" :: "n"(N) : "memory");
}

__device__ __forceinline__ void split4(const float4& x, uint2& hi, uint2& lo) {
    float v[4] = {x.x, x.y, x.z, x.w};
    unsigned int hw[2], lw[2];
#pragma unroll
    for (int p = 0; p < 2; p++) {
        __nv_bfloat16 h0 = __float2bfloat16(v[2 * p]);
        __nv_bfloat16 h1 = __float2bfloat16(v[2 * p + 1]);
        float r0 = v[2 * p]     - __bfloat162float(h0);
        float r1 = v[2 * p + 1] - __bfloat162float(h1);
        hw[p] = (unsigned)__bfloat16_as_ushort(h0) |
                ((unsigned)__bfloat16_as_ushort(h1) << 16);
        lw[p] = (unsigned)__bfloat16_as_ushort(__float2bfloat16(r0)) |
                ((unsigned)__bfloat16_as_ushort(__float2bfloat16(r1)) << 16);
    }
    hi = make_uint2(hw[0], hw[1]);
    lo = make_uint2(lw[0], lw[1]);
}

__device__ __forceinline__ void ldsm_x4(uint32_t* r, uint32_t a) {
    asm volatile("ldmatrix.sync.aligned.m8n8.x4.shared.b16 {%0,%1,%2,%3}, [%4];"
                 : "=r"(r[0]), "=r"(r[1]), "=r"(r[2]), "=r"(r[3]) : "r"(a));
}
__device__ __forceinline__ void ldsm_x4_t(uint32_t* r, uint32_t a) {
    asm volatile("ldmatrix.sync.aligned.m8n8.x4.trans.shared.b16 {%0,%1,%2,%3}, [%4];"
                 : "=r"(r[0]), "=r"(r[1]), "=r"(r[2]), "=r"(r[3]) : "r"(a));
}
__device__ __forceinline__ void mma_bf16(float* c, const uint32_t* a,
                                         uint32_t b0, uint32_t b1) {
    asm volatile(
        "mma.sync.aligned.m16n8k16.row.col.f32.bf16.bf16.f32 "
        "{%0,%1,%2,%3}, {%4,%5,%6,%7}, {%8,%9}, {%0,%1,%2,%3};"
        : "+f"(c[0]), "+f"(c[1]), "+f"(c[2]), "+f"(c[3])
        : "r"(a[0]), "r"(a[1]), "r"(a[2]), "r"(a[3]), "r"(b0), "r"(b1));
}

// reconstruct fp32 pair from packed bf16 hi/lo words
__device__ __forceinline__ float2 bfpair(unsigned int h, unsigned int l) {
    float hx = __bfloat162float(__ushort_as_bfloat16((unsigned short)(h & 0xffff)));
    float hy = __bfloat162float(__ushort_as_bfloat16((unsigned short)(h >> 16)));
    float lx = __bfloat162float(__ushort_as_bfloat16((unsigned short)(l & 0xffff)));
    float ly = __bfloat162float(__ushort_as_bfloat16((unsigned short)(l >> 16)));
    return make_float2(hx + lx, hy + ly);
}

// ---------------- K0: E0 hi/lo split + V hi/lo split (merged launch) ---------
__global__ void k_init_prep(const float* __restrict__ u, const float* __restrict__ it,
                            const float* __restrict__ v) {
    if (blockIdx.x < EW_BLOCKS) {
        int i = blockIdx.x * blockDim.x + threadIdx.x;
        if (i < (NPAD - N_TOT) * D / 4) {
            uint2 z = make_uint2(0u, 0u);
            *(uint2*)(g_e0h + (size_t)N_TOT * D + i * 4) = z;
            *(uint2*)(g_e0l + (size_t)N_TOT * D + i * 4) = z;
        }
        if (i >= NTOT4) return;
        int e = i << 2;
        float4 t;
        if (e < NU_ELEMS) t = *(const float4*)(u + e);
        else              t = *(const float4*)(it + (e - NU_ELEMS));
        uint2 hi, lo;
        split4(t, hi, lo);
        *(uint2*)(g_e0h + e) = hi;
        *(uint2*)(g_e0l + e) = lo;
    } else {
        size_t i = (size_t)(blockIdx.x - EW_BLOCKS) * blockDim.x + threadIdx.x;
        size_t e = i * 8;
        int n = (int)(e >> 9);
        uint2 h0, l0, h1, l1;
        if (n < N_TOT) {
            float4 x0 = *(const float4*)(v + e);
            float4 x1 = *(const float4*)(v + e + 4);
            split4(x0, h0, l0);
            split4(x1, h1, l1);
        } else {
            h0 = l0 = h1 = l1 = make_uint2(0u, 0u);
        }
        *(uint4*)(g_vh + e) = make_uint4(h0.x, h0.y, h1.x, h1.y);
        *(uint4*)(g_vl + e) = make_uint4(l0.x, l0.y, l1.x, l1.y);
    }
}

// ---------------- reduce partials -> W_l ; wh/wl [f][d] ; Wsum ---------------
template <int L>
__global__ void k_reduce1(const float* __restrict__ filt) {
    __shared__ float2 buf[8][32];
    const int f   = blockIdx.x;                 // 0..511
    const int sub = threadIdx.x >> 5;           // warp id = 0..7
    const int d2  = threadIdx.x & 31;           // float2 column
    const int mt  = f >> 7, fl = f & 127;
    const float* base = g_p1 + fl * 64 + d2 * 2;

    float2 s = make_float2(0.f, 0.f);
    for (int ks = sub; ks < KSPLITS; ks += 8) {
        float2 t = *(const float2*)(base + (size_t)((ks << 2) + mt) * 8192);
        s.x += t.x; s.y += t.y;
    }
    buf[sub][d2] = s;
    __syncthreads();
    if (sub != 0) return;

#pragma unroll
    for (int k = 1; k < 8; k++) {
        float2 t = buf[k][d2];
        s.x += t.x; s.y += t.y;
    }
    float fc = filt[f];
    s.x *= fc; s.y *= fc;
    float* wsp = g_ws + f * 64 + d2 * 2;
    float2 tot = s;
    if (L == 0) {
        *(float2*)wsp = s;
    } else {
        float2 o = *(const float2*)wsp;
        tot = make_float2(o.x + s.x, o.y + s.y);
        if (L == 1) *(float2*)wsp = tot;
    }
    float2 wv = (L < 2) ? s : tot;
    __nv_bfloat16 hx = __float2bfloat16(wv.x);
    __nv_bfloat16 hy = __float2bfloat16(wv.y);
    float rx = wv.x - __bfloat162float(hx);
    float ry = wv.y - __bfloat162float(hy);
    unsigned int hw = (unsigned)__bfloat16_as_ushort(hx) |
                      ((unsigned)__bfloat16_as_ushort(hy) << 16);
    unsigned int lw = (unsigned)__bfloat16_as_ushort(__float2bfloat16(rx)) |
                      ((unsigned)__bfloat16_as_ushort(__float2bfloat16(ry)) << 16);
    *(unsigned int*)(g_wh + f * 64 + d2 * 2) = hw;
    *(unsigned int*)(g_wl + f * 64 + d2 * 2) = lw;
}

// ---------------- pipelined warp-MMA GEMM ----------------
// C[128 x 64] = A[128 x K] * B[64 x K]^T, hi/lo bf16 split (3 MMA terms)
// MODE 0: GEMM1, B = E0 pair   -> g_p1 partial      (A trans from [n][512])
// MODE 3: GEMM1, B = E_l pair  -> g_p1 partial
// MODE 1: GEMM2, B = W [f][d]  -> writes E hi/lo    (A plain; B trans path)
// MODE 2: final, B = Wsum[f][d]-> out = (E0 + C)/4
// 3 slots x 24 KB, 3 CTAs/SM (24 warps) - occupancy push.
template <int MODE>
__global__ __launch_bounds__(256, 3) void k_gemm(float* __restrict__ outp) {
    constexpr bool G1 = (MODE == 0 || MODE == 3);
    extern __shared__ char smraw[];
    const uint32_t sm0 = (smem_u32(smraw) + 1023) & ~1023u;

    const int tid  = threadIdx.x;
    const int w    = tid >> 5;
    const int lane = tid & 31;

    int m0, c0, nc;
    if (G1) {
        int mt = blockIdx.x & 3;
        int ks = blockIdx.x >> 2;
        m0 = mt * 128;                         // f-tile origin
        c0 = ks * CH_PER_SPLIT;
        nc = min(CH_PER_SPLIT, CH_TOT - c0);
    } else {
        m0 = blockIdx.x * 128;                 // n-tile origin
        c0 = 0;
        nc = F / KC;                           // 16
    }

    const unsigned short* bhp = (MODE == 0) ? g_e0h : (MODE == 3) ? g_eh : g_wh;
    const unsigned short* blp = (MODE == 0) ? g_e0l : (MODE == 3) ? g_el : g_wl;

    float acc[8][4];
#pragma unroll
    for (int nt = 0; nt < 8; nt++)
#pragma unroll
        for (int j = 0; j < 4; j++) acc[nt][j] = 0.f;

    auto stage = [&](int ch) {
        if (ch >= nc) return;
        const int k0 = (c0 + ch) * KC;
        const uint32_t sbuf = sm0 + (uint32_t)(ch % NSTAGE) * STAGE;
        if (G1) {
            for (int j = tid; j < 512; j += 256) {
                int n = j >> 4, seg = (j >> 3) & 1, q = j & 7;
                size_t src = (size_t)(k0 + n) * F + m0 + seg * 64 + q * 8;
                uint32_t d = seg * 4096 + swz(n * 128 + q * 16);
                cp16(sbuf + d,           g_vh + src);
                cp16(sbuf + A_OFF_L + d, g_vl + src);
            }
            {
                int n = tid >> 3, q = tid & 7;
                size_t src = (size_t)(k0 + n) * D + q * 8;
                uint32_t d = swz(n * 128 + q * 16);
                cp16(sbuf + B_OFF_H + d, bhp + src);
                cp16(sbuf + B_OFF_L + d, blp + src);
            }
        } else {
            for (int j = tid; j < 512; j += 256) {
                int m = j >> 2, q = j & 3;
                size_t src = (size_t)(m0 + m) * F + k0 + q * 8;
                uint32_t d = swz(m * 64 + q * 16);
                cp16(sbuf + d,           g_vh + src);
                cp16(sbuf + A_OFF_L + d, g_vl + src);
            }
            {
                // B = W rows [KC f][64 d], 128B rows (same shape as G1's B)
                int row = tid >> 3, q = tid & 7;
                size_t src = (size_t)(k0 + row) * D + q * 8;
                uint32_t d = swz(row * 128 + q * 16);
                cp16(sbuf + B_OFF_H + d, bhp + src);
                cp16(sbuf + B_OFF_L + d, blp + src);
            }
        }
    };

    // fragment addressing
    const int a_k   = (lane & 7) | ((lane & 16) >> 1);        // G1 (trans A)
    const uint32_t a_seg = (uint32_t)(w >> 2) * 4096;
    const uint32_t a_f2  = (uint32_t)((w * 16 + (lane & 8)) & 63) * 2;
    const int bt_k  = lane & 15;                              // trans B (all modes)
    const int bt_n8 = ((lane >> 4) & 1) * 8;
    const int a_row  = w * 16 + (lane & 15);                  // plain A
    const int a_colh = (lane >> 4) * 8;

    auto compute = [&](int ch) {
        const uint32_t buf = sm0 + (uint32_t)(ch % NSTAGE) * STAGE;
        const uint32_t sAh = buf, sAl = buf + A_OFF_L;
        const uint32_t sBh = buf + B_OFF_H, sBl = buf + B_OFF_L;
#pragma unroll
        for (int ks = 0; ks < KC / 16; ks++) {
            uint32_t ah[4], al[4];
            if (G1) {
                uint32_t ao = a_seg + swz((uint32_t)((ks * 16 + a_k) * 128) + a_f2);
                ldsm_x4_t(ah, sAh + ao);
                ldsm_x4_t(al, sAl + ao);
            } else {
                uint32_t ao = swz((uint32_t)(a_row * 64 + (ks * 16 + a_colh) * 2));
                ldsm_x4(ah, sAh + ao);
                ldsm_x4(al, sAl + ao);
            }
#pragma unroll
            for (int nt2 = 0; nt2 < 4; nt2++) {
                uint32_t bh[4], bl[4];
                uint32_t bo = swz((uint32_t)((ks * 16 + bt_k) * 128 +
                                             (nt2 * 16 + bt_n8) * 2));
                ldsm_x4_t(bh, sBh + bo);
                ldsm_x4_t(bl, sBl + bo);
                float* cE = acc[2 * nt2];
                float* cO = acc[2 * nt2 + 1];
                mma_bf16(cE, ah, bh[0], bh[1]);
                mma_bf16(cE, ah, bl[0], bl[1]);
                mma_bf16(cE, al, bh[0], bh[1]);
                mma_bf16(cO, ah, bh[2], bh[3]);
                mma_bf16(cO, ah, bl[2], bl[3]);
                mma_bf16(cO, al, bh[2], bh[3]);
            }
        }
    };

    // ---- pipeline: 3 slots, lookahead 2, two barriers per chunk ----
    // slot (ch+2)%3 was last read at compute(ch-1), which is separated from
    // this stage by iter ch-1's trailing sync. wait<1> completes group ch.
    stage(0);
    cp_commit();
    stage(1);
    cp_commit();
    for (int ch = 0; ch < nc; ch++) {
        cp_wait<1>();
        __syncthreads();
        stage(ch + 2);
        cp_commit();
        compute(ch);
        __syncthreads();
    }

    // ---- epilogue ----
    const int r0   = w * 16 + (lane >> 2);
    const int ncol = 2 * (lane & 3);
    if (G1) {
        float* out = g_p1 + (size_t)blockIdx.x * 8192;
#pragma unroll
        for (int nt = 0; nt < 8; nt++) {
            int n = nt * 8 + ncol;
            *(float2*)(out + r0 * 64 + n)       = make_float2(acc[nt][0], acc[nt][1]);
            *(float2*)(out + (r0 + 8) * 64 + n) = make_float2(acc[nt][2], acc[nt][3]);
        }
    } else if (MODE == 1) {
#pragma unroll
        for (int half = 0; half < 2; half++) {
            int m = m0 + r0 + half * 8;
            if (m >= N_TOT) continue;
            unsigned short* ehp = g_eh + (size_t)m * D;
            unsigned short* elp = g_el + (size_t)m * D;
#pragma unroll
            for (int nt = 0; nt < 8; nt++) {
                int n = nt * 8 + ncol;
                float cx = acc[nt][half * 2], cy = acc[nt][half * 2 + 1];
                __nv_bfloat16 hx = __float2bfloat16(cx);
                __nv_bfloat16 hy = __float2bfloat16(cy);
                float rx = cx - __bfloat162float(hx);
                float ry = cy - __bfloat162float(hy);
                unsigned int hw = (unsigned)__bfloat16_as_ushort(hx) |
                                  ((unsigned)__bfloat16_as_ushort(hy) << 16);
                unsigned int lw = (unsigned)__bfloat16_as_ushort(__float2bfloat16(rx)) |
                                  ((unsigned)__bfloat16_as_ushort(__float2bfloat16(ry)) << 16);
                *(unsigned int*)(ehp + n) = hw;
                *(unsigned int*)(elp + n) = lw;
            }
        }
    } else {   // MODE 2: out = (E0 + C)/4
#pragma unroll
        for (int half = 0; half < 2; half++) {
            int m = m0 + r0 + half * 8;
            if (m >= N_TOT) continue;
            const unsigned short* e0hp = g_e0h + (size_t)m * D;
            const unsigned short* e0lp = g_e0l + (size_t)m * D;
            float* op = outp + (size_t)m * D;
#pragma unroll
            for (int nt = 0; nt < 8; nt++) {
                int n = nt * 8 + ncol;
                float cx = acc[nt][half * 2], cy = acc[nt][half * 2 + 1];
                unsigned int hv = *(const unsigned int*)(e0hp + n);
                unsigned int lv = *(const unsigned int*)(e0lp + n);
                float2 e = bfpair(hv, lv);
                *(float2*)(op + n) = make_float2((e.x + cx) * 0.25f,
                                                 (e.y + cy) * 0.25f);
            }
        }
    }
}

// ---------------- launcher ----------------
extern "C" void kernel_launch(void* const* d_in, const int* in_sizes, int n_in,
                              void* d_out, int out_size) {
    const float* user    = (const float*)d_in[0];
    const float* item    = (const float*)d_in[1];
    const float* v       = (const float*)d_in[2];
    const float* filters = (const float*)d_in[3];
    float* out = (float*)d_out;

    cudaFuncSetAttribute(k_gemm<0>, cudaFuncAttributeMaxDynamicSharedMemorySize, GEMM_SMEM);
    cudaFuncSetAttribute(k_gemm<1>, cudaFuncAttributeMaxDynamicSharedMemorySize, GEMM_SMEM);
    cudaFuncSetAttribute(k_gemm<2>, cudaFuncAttributeMaxDynamicSharedMemorySize, GEMM_SMEM);
    cudaFuncSetAttribute(k_gemm<3>, cudaFuncAttributeMaxDynamicSharedMemorySize, GEMM_SMEM);

    k_init_prep<<<EW_BLOCKS + PREP_BLOCKS, 256>>>(user, item, v);

    // layer 1
    k_gemm<0><<<KSPLITS * 4, 256, GEMM_SMEM>>>(nullptr);   // P1 = V^T E0
    k_reduce1<0><<<512, 256>>>(filters);                   // W1; ws = W1
    k_gemm<1><<<NPAD / 128, 256, GEMM_SMEM>>>(nullptr);    // E1 = V W1
    // layer 2
    k_gemm<3><<<KSPLITS * 4, 256, GEMM_SMEM>>>(nullptr);   // P2 = V^T E1
    k_reduce1<1><<<512, 256>>>(filters + F);               // W2; ws += W2
    k_gemm<1><<<NPAD / 128, 256, GEMM_SMEM>>>(nullptr);    // E2 = V W2
    // layer 3
    k_gemm<3><<<KSPLITS * 4, 256, GEMM_SMEM>>>(nullptr);   // P3 = V^T E2
    k_reduce1<2><<<512, 256>>>(filters + 2 * F);           // Wsum hi/lo (merged)

    k_gemm<2><<<NPAD / 128, 256, GEMM_SMEM>>>(out);        // out = (E0 + V Wsum)/4
}